// round 2
// baseline (speedup 1.0000x reference)
#include <cuda_runtime.h>
#include <cstddef>

#define Hd   50
#define HP   52      // padded row stride (words); 8B-aligned rows, conflict-benign
#define HP2  26      // row stride in 64-bit units
#define NJ2  25      // 50/2 j-pairs
#define G4   200     // 4*H
#define Bsz  4096
#define Tt   256
#define EPB  16      // batch elements per block
#define EPT  4       // elements per thread
#define NTHR 200

typedef unsigned long long ull;

// Ping-pong inter-layer activations: [T][B][H] fp32
__device__ float g_ysA[(size_t)Tt * Bsz * Hd];
__device__ float g_ysB[(size_t)Tt * Bsz * Hd];

__device__ __forceinline__ ull ffma2(ull a, ull b, ull c) {
    ull d;
    asm("fma.rn.f32x2 %0, %1, %2, %3;" : "=l"(d) : "l"(a), "l"(b), "l"(c));
    return d;
}
__device__ __forceinline__ float f2sum(ull v) {
    float lo, hi;
    asm("mov.b64 {%0, %1}, %2;" : "=f"(lo), "=f"(hi) : "l"(v));
    return lo + hi;
}
__device__ __forceinline__ float sigf(float x) {
    return __fdividef(1.0f, 1.0f + __expf(-x));
}
__device__ __forceinline__ float tanhf_fast(float x) {
    return 1.0f - __fdividef(2.0f, __expf(2.0f * x) + 1.0f);
}

// One LSTM layer over the full sequence for a tile of EPB batch elements.
// Thread mapping: u = tid>>2 (hidden unit), eg = tid&3 (element group of 4).
// Warp lanes therefore span 8 units x 4 groups -> weight LDS multicasts 8-way.
__global__ __launch_bounds__(NTHR, 2)
void lstm_layer_kernel(const float* __restrict__ x,
                       const float* __restrict__ ys_in,
                       const float* __restrict__ w_ih,
                       const float* __restrict__ w_hh,
                       const float* __restrict__ bias,
                       float* __restrict__ ys_out,
                       const float* __restrict__ fc_w,
                       const float* __restrict__ fc_b,
                       float* __restrict__ out,
                       int layer0)
{
    extern __shared__ float sm[];
    float* Wh  = sm;                    // [200][HP]
    float* Wi  = Wh + G4 * HP;          // [200][HP] (unused for layer0)
    float* hb0 = Wi + G4 * HP;          // [16][HP] h ping
    float* hb1 = hb0 + EPB * HP;        // [16][HP] h pong
    float* ib0 = hb1 + EPB * HP;        // [16][HP] input ping
    float* ib1 = ib0 + EPB * HP;        // [16][HP] input pong

    const int tid   = threadIdx.x;
    const int e0    = blockIdx.x * EPB;
    const int u     = tid >> 2;
    const int eg    = tid & 3;
    const int ebase = eg * EPT;

    // ---- load weights into smem (once per pass) ----
    for (int idx = tid; idx < G4 * Hd; idx += NTHR) {
        int g = idx / Hd, j = idx - g * Hd;
        Wh[g * HP + j] = w_hh[idx];
        if (!layer0) Wi[g * HP + j] = w_ih[idx];
    }
    // ---- init state buffers (incl. pad columns) ----
    for (int idx = tid; idx < EPB * HP; idx += NTHR) {
        hb0[idx] = 0.0f; hb1[idx] = 0.0f; ib0[idx] = 0.0f; ib1[idx] = 0.0f;
    }

    // Precompute coalesced staging offsets: 4 (e,j) slots per thread.
    int soff[4], goff[4];
    #pragma unroll
    for (int k = 0; k < 4; k++) {
        int idx = tid + k * NTHR;
        int e = idx / Hd, j = idx - e * Hd;
        soff[k] = e * HP + j;
        goff[k] = idx;
    }

    const float bi = bias[u], bf = bias[50 + u], bg = bias[100 + u], bo = bias[150 + u];
    float wx_i = 0.f, wx_f = 0.f, wx_g = 0.f, wx_o = 0.f;
    if (layer0) { wx_i = w_ih[u]; wx_f = w_ih[50 + u]; wx_g = w_ih[100 + u]; wx_o = w_ih[150 + u]; }

    const ull* Whi = (const ull*)(Wh + (u)       * HP);
    const ull* Whf = (const ull*)(Wh + (50 + u)  * HP);
    const ull* Whg = (const ull*)(Wh + (100 + u) * HP);
    const ull* Who = (const ull*)(Wh + (150 + u) * HP);
    const ull* Wii = (const ull*)(Wi + (u)       * HP);
    const ull* Wif = (const ull*)(Wi + (50 + u)  * HP);
    const ull* Wig = (const ull*)(Wi + (100 + u) * HP);
    const ull* Wio = (const ull*)(Wi + (150 + u) * HP);

    float c[EPT];
    #pragma unroll
    for (int e = 0; e < EPT; e++) c[e] = 0.0f;

    __syncthreads();

    for (int t = 0; t < Tt; t++) {
        float* hP = (t & 1) ? hb1 : hb0;   // h(t-1)
        float* hQ = (t & 1) ? hb0 : hb1;   // h(t) target
        float* iP = (t & 1) ? ib1 : ib0;   // input(t) staging

        // ---- stage input for this timestep (coalesced) ----
        if (layer0) {
            if (tid < EPB) iP[tid * HP] = x[(size_t)(e0 + tid) * Tt + t];
        } else {
            const float* src = ys_in + ((size_t)t * Bsz + e0) * Hd;
            #pragma unroll
            for (int k = 0; k < 4; k++) iP[soff[k]] = src[goff[k]];
        }
        __syncthreads();   // h(t-1) writes + input(t) staging visible

        const ull* H2 = (const ull*)hP;
        const ull* I2 = (const ull*)iP;
        const int r0 = (ebase + 0) * HP2, r1 = (ebase + 1) * HP2,
                  r2 = (ebase + 2) * HP2, r3 = (ebase + 3) * HP2;

        ull ai[EPT], af[EPT], ag[EPT], ao[EPT];
        #pragma unroll
        for (int e = 0; e < EPT; e++) { ai[e] = 0ull; af[e] = 0ull; ag[e] = 0ull; ao[e] = 0ull; }

        // ---- recurrent dot: h(t-1) @ W_hh^T (packed f32x2 along j) ----
        #pragma unroll 5
        for (int j2 = 0; j2 < NJ2; j2++) {
            ull wi = Whi[j2], wf = Whf[j2], wg = Whg[j2], wo = Who[j2];
            ull h0 = H2[r0 + j2], h1 = H2[r1 + j2], h2 = H2[r2 + j2], h3 = H2[r3 + j2];
            ai[0] = ffma2(wi, h0, ai[0]); ai[1] = ffma2(wi, h1, ai[1]);
            ai[2] = ffma2(wi, h2, ai[2]); ai[3] = ffma2(wi, h3, ai[3]);
            af[0] = ffma2(wf, h0, af[0]); af[1] = ffma2(wf, h1, af[1]);
            af[2] = ffma2(wf, h2, af[2]); af[3] = ffma2(wf, h3, af[3]);
            ag[0] = ffma2(wg, h0, ag[0]); ag[1] = ffma2(wg, h1, ag[1]);
            ag[2] = ffma2(wg, h2, ag[2]); ag[3] = ffma2(wg, h3, ag[3]);
            ao[0] = ffma2(wo, h0, ao[0]); ao[1] = ffma2(wo, h1, ao[1]);
            ao[2] = ffma2(wo, h2, ao[2]); ao[3] = ffma2(wo, h3, ao[3]);
        }

        // ---- input dot (layers 1..4) ----
        if (!layer0) {
            #pragma unroll 5
            for (int j2 = 0; j2 < NJ2; j2++) {
                ull wi = Wii[j2], wf = Wif[j2], wg = Wig[j2], wo = Wio[j2];
                ull x0 = I2[r0 + j2], x1 = I2[r1 + j2], x2 = I2[r2 + j2], x3 = I2[r3 + j2];
                ai[0] = ffma2(wi, x0, ai[0]); ai[1] = ffma2(wi, x1, ai[1]);
                ai[2] = ffma2(wi, x2, ai[2]); ai[3] = ffma2(wi, x3, ai[3]);
                af[0] = ffma2(wf, x0, af[0]); af[1] = ffma2(wf, x1, af[1]);
                af[2] = ffma2(wf, x2, af[2]); af[3] = ffma2(wf, x3, af[3]);
                ag[0] = ffma2(wg, x0, ag[0]); ag[1] = ffma2(wg, x1, ag[1]);
                ag[2] = ffma2(wg, x2, ag[2]); ag[3] = ffma2(wg, x3, ag[3]);
                ao[0] = ffma2(wo, x0, ao[0]); ao[1] = ffma2(wo, x1, ao[1]);
                ao[2] = ffma2(wo, x2, ao[2]); ao[3] = ffma2(wo, x3, ao[3]);
            }
        }

        // ---- coalesced write-out of h(t-1) (stable: nobody writes hP this step) ----
        if (ys_out != nullptr && t > 0) {
            float* dst = ys_out + ((size_t)(t - 1) * Bsz + e0) * Hd;
            #pragma unroll
            for (int k = 0; k < 4; k++) dst[goff[k]] = hP[soff[k]];
        }

        // ---- gate nonlinearities + state update ----
        #pragma unroll
        for (int e = 0; e < EPT; e++) {
            float pi = f2sum(ai[e]) + bi;
            float pf = f2sum(af[e]) + bf;
            float pg = f2sum(ag[e]) + bg;
            float po = f2sum(ao[e]) + bo;
            if (layer0) {
                float xv = iP[(ebase + e) * HP];
                pi += wx_i * xv; pf += wx_f * xv; pg += wx_g * xv; po += wx_o * xv;
            }
            float iv = sigf(pi);
            float fv = sigf(pf);
            float gv = tanhf_fast(pg);
            float ov = sigf(po);
            c[e] = fv * c[e] + iv * gv;
            hQ[(ebase + e) * HP + u] = ov * tanhf_fast(c[e]);
        }
        // no second sync: next iteration's loop-top sync covers hQ writes
    }

    __syncthreads();
    float* hfin = (Tt & 1) ? hb1 : hb0;  // buffer written at t = Tt-1

    if (ys_out != nullptr) {
        float* dst = ys_out + ((size_t)(Tt - 1) * Bsz + e0) * Hd;
        #pragma unroll
        for (int k = 0; k < 4; k++) dst[goff[k]] = hfin[soff[k]];
    }
    if (out != nullptr && tid < EPB) {
        float s = fc_b[0];
        #pragma unroll 10
        for (int j = 0; j < Hd; j++) s += hfin[tid * HP + j] * fc_w[j];
        out[e0 + tid] = s;
    }
}

extern "C" void kernel_launch(void* const* d_in, const int* in_sizes, int n_in,
                              void* d_out, int out_size)
{
    const float* x     = (const float*)d_in[0];  // [B,T,1]
    const float* w_ih0 = (const float*)d_in[1];  // [200,1]
    const float* w_hh0 = (const float*)d_in[2];  // [200,50]
    const float* b0    = (const float*)d_in[3];  // [200]
    const float* w_ih  = (const float*)d_in[4];  // [4,200,50]
    const float* w_hh  = (const float*)d_in[5];  // [4,200,50]
    const float* b     = (const float*)d_in[6];  // [4,200]
    const float* fc_w  = (const float*)d_in[7];  // [1,50]
    const float* fc_b  = (const float*)d_in[8];  // [1]
    float* out = (float*)d_out;

    float *ysA = nullptr, *ysB = nullptr;
    cudaGetSymbolAddress((void**)&ysA, g_ysA);
    cudaGetSymbolAddress((void**)&ysB, g_ysB);

    const int smem = (2 * G4 * HP + 4 * EPB * HP) * (int)sizeof(float);
    cudaFuncSetAttribute(lstm_layer_kernel,
                         cudaFuncAttributeMaxDynamicSharedMemorySize, smem);

    const dim3 grid(Bsz / EPB);   // 256 blocks
    const dim3 block(NTHR);       // 200 threads

    // Layer 0: input x (Din=1) -> ysA
    lstm_layer_kernel<<<grid, block, smem>>>(
        x, nullptr, w_ih0, w_hh0, b0, ysA, nullptr, nullptr, nullptr, 1);

    // Layers 1..3: ping-pong ysA/ysB
    const float* src = ysA;
    float* dst = ysB;
    for (int l = 0; l < 3; l++) {
        lstm_layer_kernel<<<grid, block, smem>>>(
            nullptr, src, w_ih + (size_t)l * G4 * Hd, w_hh + (size_t)l * G4 * Hd,
            b + (size_t)l * G4, dst, nullptr, nullptr, nullptr, 0);
        const float* tmp = dst; dst = (float*)src; src = tmp;
    }

    // Layer 4: no ys_out, fused FC head -> out
    lstm_layer_kernel<<<grid, block, smem>>>(
        nullptr, src, w_ih + (size_t)3 * G4 * Hd, w_hh + (size_t)3 * G4 * Hd,
        b + (size_t)3 * G4, nullptr, fc_w, fc_b, out, 0);
}